// round 1
// baseline (speedup 1.0000x reference)
#include <cuda_runtime.h>
#include <cstddef>

#define B_ 8
#define C_ 512
#define H_ 2048
#define GROUPS_ 32
#define CG_ (C_ / GROUPS_)          // 16
#define CH_ ((size_t)C_ * H_)       // 1048576
#define HH_ ((size_t)H_ * H_)       // 4194304

// ---------------- scratch (device globals; no allocation allowed) ----------
__device__ float g_hn[B_ * C_ * H_];
__device__ float g_q [B_ * C_ * H_];
__device__ float g_k [B_ * C_ * H_];
__device__ float g_v [B_ * C_ * H_];
__device__ float g_w [B_ * H_ * H_];   // attention scores / probs (128 MB)
__device__ float g_h [B_ * C_ * H_];

// ---------------- GroupNorm ------------------------------------------------
// grid = B*GROUPS blocks, 256 threads. Each block: one (b, g) group of
// 16 channels x 2048 = 32768 floats. Two passes (stats, normalize).
__global__ __launch_bounds__(256) void groupnorm_kernel(
    const float* __restrict__ x, const float* __restrict__ gamma,
    const float* __restrict__ beta, float* __restrict__ hn)
{
    const int b = blockIdx.x >> 5;
    const int g = blockIdx.x & 31;
    const size_t base = ((size_t)b * C_ + (size_t)g * CG_) * H_;
    const float4* xp4 = (const float4*)(x + base);
    float4* hp4 = (float4*)(hn + base);
    const int t = threadIdx.x;
    const int n4 = (CG_ * H_) / 4;   // 8192

    float s = 0.f, s2 = 0.f;
    for (int i = t; i < n4; i += 256) {
        float4 v = xp4[i];
        s  += v.x + v.y + v.z + v.w;
        s2 += v.x * v.x + v.y * v.y + v.z * v.z + v.w * v.w;
    }
    __shared__ float rs[8], rs2[8];
    #pragma unroll
    for (int o = 16; o; o >>= 1) {
        s  += __shfl_xor_sync(0xffffffffu, s,  o);
        s2 += __shfl_xor_sync(0xffffffffu, s2, o);
    }
    if ((t & 31) == 0) { rs[t >> 5] = s; rs2[t >> 5] = s2; }
    __syncthreads();
    if (t == 0) {
        float S = 0.f, S2 = 0.f;
        #pragma unroll
        for (int i = 0; i < 8; i++) { S += rs[i]; S2 += rs2[i]; }
        const float inv_n = 1.0f / (CG_ * H_);
        float mean = S * inv_n;
        float var  = S2 * inv_n - mean * mean;
        rs[0]  = mean;
        rs2[0] = rsqrtf(var + 1e-6f);
    }
    __syncthreads();
    const float mean = rs[0], inv = rs2[0];

    for (int i = t; i < n4; i += 256) {
        int c = g * CG_ + ((i * 4) >> 11);           // channel of this float4
        float gm = gamma[c] * inv;
        float bt = beta[c] - mean * gm;
        float4 v = xp4[i];
        v.x = v.x * gm + bt;
        v.y = v.y * gm + bt;
        v.z = v.z * gm + bt;
        v.w = v.w * gm + bt;
        hp4[i] = v;
    }
}

// ---------------- Generic batched SGEMM ------------------------------------
// C[m,n] = alpha * sum_k A(m,k)*B(k,n)  (+ bias[m]) (+ resid[m,n])
// TRANSA=0: A(m,k) = A[m*K + k]   (row-major, K contiguous)
// TRANSA=1: A(m,k) = A[k*M + m]   (stored [K][M], M contiguous)
// TRANSB=0: B(k,n) = B[k*N + n]   (row-major, N contiguous)
// TRANSB=1: B(k,n) = B[n*K + k]   (stored [N][K], K contiguous)
// Block tile 128x128, BK=8, 256 threads, 8x8 per-thread microtile.
// Requires M,N % 128 == 0, K % 8 == 0 (always true here).
template<int TRANSA, int TRANSB, bool BIAS, bool RESID>
__global__ __launch_bounds__(256) void gemm_kernel(
    const float* __restrict__ Aall, const float* __restrict__ Ball,
    float* __restrict__ Call, const float* __restrict__ bias,
    const float* __restrict__ residall,
    int M, int N, int K,
    long sA, long sB, long sC, float alpha)
{
    const int bz = blockIdx.z;
    const float* A = Aall + (size_t)bz * sA;
    const float* B = Ball + (size_t)bz * sB;
    float* Cp = Call + (size_t)bz * sC;
    const int bm = blockIdx.y * 128;
    const int bn = blockIdx.x * 128;

    __shared__ float As[8][128];
    __shared__ float Bs[8][128];

    const int t  = threadIdx.x;
    const int tx = t & 15;       // column group (8 cols)
    const int ty = t >> 4;       // row group (8 rows)

    float acc[8][8];
    #pragma unroll
    for (int i = 0; i < 8; i++)
        #pragma unroll
        for (int j = 0; j < 8; j++) acc[i][j] = 0.f;

    for (int k0 = 0; k0 < K; k0 += 8) {
        // ---- load A tile -> As[k][m]
        if (TRANSA == 0) {
            int m  = t >> 1;
            int kk = (t & 1) * 4;
            float4 v = *(const float4*)(A + (size_t)(bm + m) * K + k0 + kk);
            As[kk + 0][m] = v.x; As[kk + 1][m] = v.y;
            As[kk + 2][m] = v.z; As[kk + 3][m] = v.w;
        } else {
            int kk = t >> 5;
            int m  = (t & 31) * 4;
            *(float4*)&As[kk][m] = *(const float4*)(A + (size_t)(k0 + kk) * M + bm + m);
        }
        // ---- load B tile -> Bs[k][n]
        if (TRANSB == 0) {
            int kk = t >> 5;
            int n  = (t & 31) * 4;
            *(float4*)&Bs[kk][n] = *(const float4*)(B + (size_t)(k0 + kk) * N + bn + n);
        } else {
            int n  = t >> 1;
            int kk = (t & 1) * 4;
            float4 v = *(const float4*)(B + (size_t)(bn + n) * K + k0 + kk);
            Bs[kk + 0][n] = v.x; Bs[kk + 1][n] = v.y;
            Bs[kk + 2][n] = v.z; Bs[kk + 3][n] = v.w;
        }
        __syncthreads();

        #pragma unroll
        for (int k = 0; k < 8; k++) {
            float a[8], b[8];
            *(float4*)(a)     = *(const float4*)&As[k][ty * 8];
            *(float4*)(a + 4) = *(const float4*)&As[k][ty * 8 + 4];
            *(float4*)(b)     = *(const float4*)&Bs[k][tx * 8];
            *(float4*)(b + 4) = *(const float4*)&Bs[k][tx * 8 + 4];
            #pragma unroll
            for (int i = 0; i < 8; i++)
                #pragma unroll
                for (int j = 0; j < 8; j++)
                    acc[i][j] += a[i] * b[j];
        }
        __syncthreads();
    }

    // ---- epilogue
    const float* resid = RESID ? (residall + (size_t)bz * sC) : nullptr;
    #pragma unroll
    for (int i = 0; i < 8; i++) {
        const int m = bm + ty * 8 + i;
        float bi = BIAS ? bias[m] : 0.f;
        float* crow = Cp + (size_t)m * N + bn + tx * 8;
        #pragma unroll
        for (int j = 0; j < 8; j += 4) {
            float4 r;
            r.x = acc[i][j + 0] * alpha + bi;
            r.y = acc[i][j + 1] * alpha + bi;
            r.z = acc[i][j + 2] * alpha + bi;
            r.w = acc[i][j + 3] * alpha + bi;
            if (RESID) {
                float4 q = *(const float4*)(resid + (size_t)m * N + bn + tx * 8 + j);
                r.x += q.x; r.y += q.y; r.z += q.z; r.w += q.w;
            }
            *(float4*)(crow + j) = r;
        }
    }
}

// ---------------- Softmax over last axis (rows of 2048) --------------------
// grid = B*H rows, 256 threads; each thread owns 8 strided elements in regs.
__global__ __launch_bounds__(256) void softmax_kernel(float* __restrict__ w)
{
    float* p = w + (size_t)blockIdx.x * H_;
    const int t = threadIdx.x;
    float v[8];
    float mx = -3.4e38f;
    #pragma unroll
    for (int i = 0; i < 8; i++) {
        v[i] = p[t + i * 256];
        mx = fmaxf(mx, v[i]);
    }
    __shared__ float red[8], red2[8];
    #pragma unroll
    for (int o = 16; o; o >>= 1) mx = fmaxf(mx, __shfl_xor_sync(0xffffffffu, mx, o));
    if ((t & 31) == 0) red[t >> 5] = mx;
    __syncthreads();
    mx = red[0];
    #pragma unroll
    for (int i = 1; i < 8; i++) mx = fmaxf(mx, red[i]);

    float s = 0.f;
    #pragma unroll
    for (int i = 0; i < 8; i++) { v[i] = __expf(v[i] - mx); s += v[i]; }
    #pragma unroll
    for (int o = 16; o; o >>= 1) s += __shfl_xor_sync(0xffffffffu, s, o);
    if ((t & 31) == 0) red2[t >> 5] = s;
    __syncthreads();
    s = 0.f;
    #pragma unroll
    for (int i = 0; i < 8; i++) s += red2[i];
    const float inv = 1.0f / s;
    #pragma unroll
    for (int i = 0; i < 8; i++) p[t + i * 256] = v[i] * inv;
}

// ---------------- launch ---------------------------------------------------
extern "C" void kernel_launch(void* const* d_in, const int* in_sizes, int n_in,
                              void* d_out, int out_size)
{
    const float* x     = (const float*)d_in[0];
    const float* gamma = (const float*)d_in[1];
    const float* beta  = (const float*)d_in[2];
    const float* wq    = (const float*)d_in[3];
    const float* bq    = (const float*)d_in[4];
    const float* wk    = (const float*)d_in[5];
    const float* bk    = (const float*)d_in[6];
    const float* wv    = (const float*)d_in[7];
    const float* bv    = (const float*)d_in[8];
    const float* wp    = (const float*)d_in[9];
    const float* bp    = (const float*)d_in[10];
    float* out = (float*)d_out;

    float *hn, *q, *k, *v, *w, *hb;
    cudaGetSymbolAddress((void**)&hn, g_hn);
    cudaGetSymbolAddress((void**)&q,  g_q);
    cudaGetSymbolAddress((void**)&k,  g_k);
    cudaGetSymbolAddress((void**)&v,  g_v);
    cudaGetSymbolAddress((void**)&w,  g_w);
    cudaGetSymbolAddress((void**)&hb, g_h);

    const long CH = (long)CH_;
    const long HH = (long)HH_;
    const float scale = 0.044194173824159216f;  // 512^-0.5

    // 1) GroupNorm
    groupnorm_kernel<<<B_ * GROUPS_, 256>>>(x, gamma, beta, hn);

    // 2) Q/K/V 1x1 convs: [512x512] @ [512x2048] per batch, weight shared
    dim3 gconv(H_ / 128, C_ / 128, B_);   // (16, 4, 8)
    gemm_kernel<0, 0, true, false><<<gconv, 256>>>(wq, hn, q, bq, nullptr,
        C_, H_, C_, 0, CH, CH, 1.0f);
    gemm_kernel<0, 0, true, false><<<gconv, 256>>>(wk, hn, k, bk, nullptr,
        C_, H_, C_, 0, CH, CH, 1.0f);
    gemm_kernel<0, 0, true, false><<<gconv, 256>>>(wv, hn, v, bv, nullptr,
        C_, H_, C_, 0, CH, CH, 1.0f);

    // 3) scores w[b,i,j] = scale * sum_c q[b,c,i] k[b,c,j]
    //    A = q (stored [K=C][M=H], M-contig -> TRANSA=1), B = k ([K=C][N=H])
    dim3 gsc(H_ / 128, H_ / 128, B_);     // (16, 16, 8)
    gemm_kernel<1, 0, false, false><<<gsc, 256>>>(q, k, w, nullptr, nullptr,
        H_, H_, C_, CH, CH, HH, scale);

    // 4) softmax over j
    softmax_kernel<<<B_ * H_, 256>>>(w);

    // 5) h[b,c,i] = sum_j v[b,c,j] w[b,i,j]
    //    A = v ([M=C][K=H] row-major), B = w (stored [N=i? no: [i][j]] = [N][K] -> TRANSB=1)
    dim3 gav(H_ / 128, C_ / 128, B_);     // (16, 4, 8)
    gemm_kernel<0, 1, false, false><<<gav, 256>>>(v, w, hb, nullptr, nullptr,
        C_, H_, H_, CH, HH, CH, 1.0f);

    // 6) proj + bias + residual
    gemm_kernel<0, 0, true, true><<<gav, 256>>>(wp, hb, out, bp, x,
        C_, H_, C_, 0, CH, CH, 1.0f);
}

// round 3
// speedup vs baseline: 2.1441x; 2.1441x over previous
#include <cuda_runtime.h>
#include <cuda_bf16.h>
#include <cstdint>
#include <cstddef>

#define B_ 8
#define C_ 512
#define H_ 2048
#define CG_ 16
#define CH_ 1048576LL      // C*H
#define HH_ 4194304LL      // H*H
#define BCH_ 8388608LL     // B*C*H
#define BHH_ 33554432LL    // B*H*H

// ---------------- scratch (device globals) ---------------------------------
__device__ __nv_bfloat16 g_hnT_h[BCH_], g_hnT_l[BCH_];   // [B][H][C]
__device__ __nv_bfloat16 g_qT_h[BCH_],  g_qT_l[BCH_];    // [B][H][C]
__device__ __nv_bfloat16 g_kT_h[BCH_],  g_kT_l[BCH_];    // [B][H][C]
__device__ __nv_bfloat16 g_v_h[BCH_],   g_v_l[BCH_];     // [B][C][H]
__device__ __nv_bfloat16 g_hT_h[BCH_],  g_hT_l[BCH_];    // [B][H][C]
__device__ float         g_w[BHH_];                      // scores fp32
__device__ __nv_bfloat16 g_p_h[BHH_],   g_p_l[BHH_];     // probs [B][H][H]
__device__ __nv_bfloat16 g_wq_h[C_*C_], g_wq_l[C_*C_];
__device__ __nv_bfloat16 g_wk_h[C_*C_], g_wk_l[C_*C_];
__device__ __nv_bfloat16 g_wv_h[C_*C_], g_wv_l[C_*C_];
__device__ __nv_bfloat16 g_wp_h[C_*C_], g_wp_l[C_*C_];

// ---------------- helpers --------------------------------------------------
__device__ __forceinline__ uint32_t smem_to_u32(const void* p) {
    uint32_t a;
    asm("{ .reg .u64 t; cvta.to.shared.u64 t, %1; cvt.u32.u64 %0, t; }"
        : "=r"(a) : "l"(p));
    return a;
}
__device__ __forceinline__ void split2(float v, __nv_bfloat16& h, __nv_bfloat16& l) {
    h = __float2bfloat16(v);
    l = __float2bfloat16(v - __bfloat162float(h));
}

#define CP16(dst, src) \
    asm volatile("cp.async.cg.shared.global [%0], [%1], 16;" :: "r"(dst), "l"(src))
#define CP_COMMIT()  asm volatile("cp.async.commit_group;" ::: "memory")
#define CP_WAIT1()   asm volatile("cp.async.wait_group 1;" ::: "memory")
#define LDM4(R, addr) \
    asm volatile("ldmatrix.sync.aligned.m8n8.x4.shared.b16 {%0,%1,%2,%3}, [%4];" \
        : "=r"((R)[0]), "=r"((R)[1]), "=r"((R)[2]), "=r"((R)[3]) : "r"(addr))
#define HMMA(d, a, b0, b1) \
    asm volatile("mma.sync.aligned.m16n8k16.row.col.f32.bf16.bf16.f32 " \
        "{%0,%1,%2,%3}, {%4,%5,%6,%7}, {%8,%9}, {%0,%1,%2,%3};" \
        : "+f"((d)[0]), "+f"((d)[1]), "+f"((d)[2]), "+f"((d)[3]) \
        : "r"((a)[0]), "r"((a)[1]), "r"((a)[2]), "r"((a)[3]), "r"(b0), "r"(b1))

// ---------------- GroupNorm: x[b,c,h] -> hnT[b,h,c] split bf16 -------------
__global__ __launch_bounds__(256) void groupnorm_kernel(
    const float* __restrict__ x, const float* __restrict__ gamma,
    const float* __restrict__ beta,
    __nv_bfloat16* __restrict__ oh, __nv_bfloat16* __restrict__ ol)
{
    const int b = blockIdx.x >> 5;
    const int g = blockIdx.x & 31;
    const size_t base = ((size_t)b * C_ + (size_t)g * CG_) * H_;
    const float4* xp4 = (const float4*)(x + base);
    const int t = threadIdx.x;

    __shared__ float rs[8], rs2[8];
    __shared__ float gmv[16], btv[16];
    __shared__ float tile[16][257];

    float s = 0.f, s2 = 0.f;
    for (int i = t; i < (CG_ * H_) / 4; i += 256) {
        float4 v = xp4[i];
        s  += v.x + v.y + v.z + v.w;
        s2 += v.x*v.x + v.y*v.y + v.z*v.z + v.w*v.w;
    }
    #pragma unroll
    for (int o = 16; o; o >>= 1) {
        s  += __shfl_xor_sync(0xffffffffu, s,  o);
        s2 += __shfl_xor_sync(0xffffffffu, s2, o);
    }
    if ((t & 31) == 0) { rs[t >> 5] = s; rs2[t >> 5] = s2; }
    __syncthreads();
    if (t == 0) {
        float S = 0.f, S2 = 0.f;
        #pragma unroll
        for (int i = 0; i < 8; i++) { S += rs[i]; S2 += rs2[i]; }
        const float inv_n = 1.0f / (CG_ * H_);
        float mean = S * inv_n;
        float var  = S2 * inv_n - mean * mean;
        rs[0]  = mean;
        rs2[0] = rsqrtf(var + 1e-6f);
    }
    __syncthreads();
    if (t < 16) {
        int c = g * CG_ + t;
        float gm = gamma[c] * rs2[0];
        gmv[t] = gm;
        btv[t] = beta[c] - rs[0] * gm;
    }
    __syncthreads();

    for (int hc = 0; hc < H_; hc += 256) {
        #pragma unroll
        for (int r = 0; r < 16; r++)
            tile[r][t] = x[base + (size_t)r * H_ + hc + t];
        __syncthreads();
        alignas(16) __nv_bfloat16 hh[16], ll[16];
        #pragma unroll
        for (int c = 0; c < 16; c++) {
            float v = tile[c][t] * gmv[c] + btv[c];
            split2(v, hh[c], ll[c]);
        }
        size_t o = (size_t)b * H_ * C_ + (size_t)(hc + t) * C_ + g * CG_;
        *(uint4*)(oh + o)     = *(uint4*)hh;
        *(uint4*)(oh + o + 8) = *(uint4*)(hh + 8);
        *(uint4*)(ol + o)     = *(uint4*)ll;
        *(uint4*)(ol + o + 8) = *(uint4*)(ll + 8);
        __syncthreads();
    }
}

// ---------------- weight split ---------------------------------------------
__global__ __launch_bounds__(256) void split_kernel(
    const float* __restrict__ src, __nv_bfloat16* __restrict__ h,
    __nv_bfloat16* __restrict__ l, int n)
{
    int i = blockIdx.x * 256 + threadIdx.x;
    if (i < n) { __nv_bfloat16 a, b; split2(src[i], a, b); h[i] = a; l[i] = b; }
}

// ---------------- mma.sync bf16x3 GEMM -------------------------------------
// D[m,n] = sum_k A[m,k]*B[n,k]; A,B split bf16 hi/lo, both K-contiguous rows.
// CTA tile 128x128, BK=32, 3-stage cp.async pipeline, 8 warps (4m x 2n),
// warp tile 32x64, mma m16n8k16, 3 passes (AhBh + AhBl + AlBh).
// EPI: 0 transposed split+bias; 1 row split+bias; 2 fp32*alpha;
//      3 transposed split; 4 fp32+bias+resid.
#define STAGE_B 40960
#define OFF_AH  0
#define OFF_AL  10240
#define OFF_BH  20480
#define OFF_BL  30720
#define SMEM_SZ (3 * STAGE_B)    // 122880

template<int EPI>
__global__ __launch_bounds__(256) void mma_gemm(
    const __nv_bfloat16* __restrict__ Ah, const __nv_bfloat16* __restrict__ Al,
    const __nv_bfloat16* __restrict__ Bh, const __nv_bfloat16* __restrict__ Bl,
    int K, long long sA, long long sB,
    float* __restrict__ Cf, long long sC,
    __nv_bfloat16* __restrict__ Oh, __nv_bfloat16* __restrict__ Ol, long long sO,
    const float* __restrict__ bias, const float* __restrict__ resid, float alpha)
{
    extern __shared__ __align__(128) char smem[];
    const uint32_t su = smem_to_u32(smem);
    const int t    = threadIdx.x;
    const int lane = t & 31;
    const int w    = t >> 5;
    const int wm   = w >> 1;       // 0..3
    const int wn   = w & 1;        // 0..1
    const int bz = blockIdx.z;
    const int bm = blockIdx.y * 128;
    const int bn = blockIdx.x * 128;
    const int Ntot = gridDim.x * 128;
    const int Mtot = gridDim.y * 128;

    // loader mapping
    const int lrow  = t >> 1;
    const int lhalf = t & 1;
    const uint32_t dofs = (uint32_t)(lrow * 80 + lhalf * 32);
    const __nv_bfloat16* pAh = Ah + (size_t)bz * sA + (size_t)(bm + lrow) * K + lhalf * 16;
    const __nv_bfloat16* pAl = Al + (size_t)bz * sA + (size_t)(bm + lrow) * K + lhalf * 16;
    const __nv_bfloat16* pBh = Bh + (size_t)bz * sB + (size_t)(bn + lrow) * K + lhalf * 16;
    const __nv_bfloat16* pBl = Bl + (size_t)bz * sB + (size_t)(bn + lrow) * K + lhalf * 16;

    float acc[2][8][4];
    #pragma unroll
    for (int a = 0; a < 2; a++)
        #pragma unroll
        for (int b = 0; b < 8; b++)
            #pragma unroll
            for (int c = 0; c < 4; c++) acc[a][b][c] = 0.f;

    const int niter = K >> 5;

#define LOAD_STAGE(s, ci) do { \
    uint32_t d = su + (uint32_t)(s) * STAGE_B + dofs; \
    const __nv_bfloat16* a_h = pAh + (size_t)(ci) * 32; \
    const __nv_bfloat16* a_l = pAl + (size_t)(ci) * 32; \
    const __nv_bfloat16* b_h = pBh + (size_t)(ci) * 32; \
    const __nv_bfloat16* b_l = pBl + (size_t)(ci) * 32; \
    CP16(d + OFF_AH, a_h); CP16(d + OFF_AH + 16, a_h + 8); \
    CP16(d + OFF_AL, a_l); CP16(d + OFF_AL + 16, a_l + 8); \
    CP16(d + OFF_BH, b_h); CP16(d + OFF_BH + 16, b_h + 8); \
    CP16(d + OFF_BL, b_l); CP16(d + OFF_BL + 16, b_l + 8); \
} while (0)

    LOAD_STAGE(0, 0); CP_COMMIT();
    LOAD_STAGE(1, 1); CP_COMMIT();

    const int arow = lane & 15;
    const int akof = (lane >> 4) * 8;
    const int brow = (lane & 7) + (lane >> 4) * 8;
    const int bkof = ((lane >> 3) & 1) * 8;

    for (int i = 0; i < niter; i++) {
        CP_WAIT1();
        __syncthreads();
        const int ls = i + 2;
        if (ls < niter) LOAD_STAGE(ls % 3, ls);
        CP_COMMIT();

        const uint32_t base = su + (uint32_t)(i % 3) * STAGE_B;
        const uint32_t As_h = base + OFF_AH, As_l = base + OFF_AL;
        const uint32_t Bs_h = base + OFF_BH, Bs_l = base + OFF_BL;
        #pragma unroll
        for (int ks = 0; ks < 2; ks++) {
            const int k0 = ks * 16;
            uint32_t ah[2][4], alr[2][4], bh[4][4], bl[4][4];
            #pragma unroll
            for (int mt = 0; mt < 2; mt++) {
                uint32_t ro = (uint32_t)((wm * 32 + mt * 16 + arow) * 80 + (k0 + akof) * 2);
                LDM4(ah[mt],  As_h + ro);
                LDM4(alr[mt], As_l + ro);
            }
            #pragma unroll
            for (int p = 0; p < 4; p++) {
                uint32_t ro = (uint32_t)((wn * 64 + p * 16 + brow) * 80 + (k0 + bkof) * 2);
                LDM4(bh[p], Bs_h + ro);
                LDM4(bl[p], Bs_l + ro);
            }
            #pragma unroll
            for (int mt = 0; mt < 2; mt++)
                #pragma unroll
                for (int p = 0; p < 4; p++) {
                    HMMA(acc[mt][2*p],   ah[mt],  bh[p][0], bh[p][1]);
                    HMMA(acc[mt][2*p+1], ah[mt],  bh[p][2], bh[p][3]);
                    HMMA(acc[mt][2*p],   ah[mt],  bl[p][0], bl[p][1]);
                    HMMA(acc[mt][2*p+1], ah[mt],  bl[p][2], bl[p][3]);
                    HMMA(acc[mt][2*p],   alr[mt], bh[p][0], bh[p][1]);
                    HMMA(acc[mt][2*p+1], alr[mt], bh[p][2], bh[p][3]);
                }
        }
    }
#undef LOAD_STAGE

    __syncthreads();   // everyone done with pipeline smem

    const int g4 = lane >> 2, t4 = lane & 3;

    if (EPI == 2) {
        #pragma unroll
        for (int mt = 0; mt < 2; mt++) {
            const int R0 = bm + wm * 32 + mt * 16 + g4;
            #pragma unroll
            for (int nt = 0; nt < 8; nt++) {
                const int Cc = bn + wn * 64 + nt * 8 + t4 * 2;
                float2 v0 = { acc[mt][nt][0] * alpha, acc[mt][nt][1] * alpha };
                float2 v1 = { acc[mt][nt][2] * alpha, acc[mt][nt][3] * alpha };
                *(float2*)(Cf + (size_t)bz * sC + (size_t)R0 * Ntot + Cc) = v0;
                *(float2*)(Cf + (size_t)bz * sC + (size_t)(R0 + 8) * Ntot + Cc) = v1;
            }
        }
    } else if (EPI == 4) {
        #pragma unroll
        for (int mt = 0; mt < 2; mt++) {
            const int R0 = bm + wm * 32 + mt * 16 + g4;
            const float bi0 = bias[R0], bi1 = bias[R0 + 8];
            #pragma unroll
            for (int nt = 0; nt < 8; nt++) {
                const int Cc = bn + wn * 64 + nt * 8 + t4 * 2;
                const size_t i0 = (size_t)bz * sC + (size_t)R0 * Ntot + Cc;
                const size_t i1 = (size_t)bz * sC + (size_t)(R0 + 8) * Ntot + Cc;
                float2 q0 = *(const float2*)(resid + i0);
                float2 q1 = *(const float2*)(resid + i1);
                float2 v0 = { acc[mt][nt][0] + bi0 + q0.x, acc[mt][nt][1] + bi0 + q0.y };
                float2 v1 = { acc[mt][nt][2] + bi1 + q1.x, acc[mt][nt][3] + bi1 + q1.y };
                *(float2*)(Cf + i0) = v0;
                *(float2*)(Cf + i1) = v1;
            }
        }
    } else if (EPI == 1) {
        #pragma unroll
        for (int mt = 0; mt < 2; mt++) {
            const int R0 = bm + wm * 32 + mt * 16 + g4;
            const float bi0 = bias[R0], bi1 = bias[R0 + 8];
            #pragma unroll
            for (int nt = 0; nt < 8; nt++) {
                const int Cc = bn + wn * 64 + nt * 8 + t4 * 2;
                const size_t i0 = (size_t)bz * sO + (size_t)R0 * Ntot + Cc;
                const size_t i1 = (size_t)bz * sO + (size_t)(R0 + 8) * Ntot + Cc;
                __nv_bfloat162 hv, lv;
                split2(acc[mt][nt][0] + bi0, hv.x, lv.x);
                split2(acc[mt][nt][1] + bi0, hv.y, lv.y);
                *(__nv_bfloat162*)(Oh + i0) = hv;
                *(__nv_bfloat162*)(Ol + i0) = lv;
                split2(acc[mt][nt][2] + bi1, hv.x, lv.x);
                split2(acc[mt][nt][3] + bi1, hv.y, lv.y);
                *(__nv_bfloat162*)(Oh + i1) = hv;
                *(__nv_bfloat162*)(Ol + i1) = lv;
            }
        }
    } else {   // EPI 0 / 3: transposed split store via smem staging
        __nv_bfloat16* sh = (__nv_bfloat16*)smem;
        __nv_bfloat16* sl = (__nv_bfloat16*)(smem + 128 * 136 * 2);
        #pragma unroll
        for (int mt = 0; mt < 2; mt++) {
            const int Rl = wm * 32 + mt * 16 + g4;
            const float bi0 = (EPI == 0) ? bias[bm + Rl] : 0.f;
            const float bi1 = (EPI == 0) ? bias[bm + Rl + 8] : 0.f;
            #pragma unroll
            for (int nt = 0; nt < 8; nt++) {
                const int Cl = wn * 64 + nt * 8 + t4 * 2;
                __nv_bfloat16 hh, ll;
                split2(acc[mt][nt][0] + bi0, hh, ll);
                sh[Cl * 136 + Rl] = hh;           sl[Cl * 136 + Rl] = ll;
                split2(acc[mt][nt][1] + bi0, hh, ll);
                sh[(Cl + 1) * 136 + Rl] = hh;     sl[(Cl + 1) * 136 + Rl] = ll;
                split2(acc[mt][nt][2] + bi1, hh, ll);
                sh[Cl * 136 + Rl + 8] = hh;       sl[Cl * 136 + Rl + 8] = ll;
                split2(acc[mt][nt][3] + bi1, hh, ll);
                sh[(Cl + 1) * 136 + Rl + 8] = hh; sl[(Cl + 1) * 136 + Rl + 8] = ll;
            }
        }
        __syncthreads();
        const int nrow = t >> 5;       // 0..7
        const int m4   = lane * 4;     // 0..124
        #pragma unroll
        for (int it = 0; it < 16; it++) {
            const int n = it * 8 + nrow;
            uint2 vh = *(uint2*)(sh + n * 136 + m4);
            uint2 vl = *(uint2*)(sl + n * 136 + m4);
            const size_t o = (size_t)bz * sO + (size_t)(bn + n) * Mtot + bm + m4;
            *(uint2*)(Oh + o) = vh;
            *(uint2*)(Ol + o) = vl;
        }
    }
}

// ---------------- Softmax: w fp32 row -> probs split bf16 ------------------
__global__ __launch_bounds__(256) void softmax_kernel(
    const float* __restrict__ w,
    __nv_bfloat16* __restrict__ ph, __nv_bfloat16* __restrict__ pl)
{
    const float* p = w + (size_t)blockIdx.x * H_;
    const int t = threadIdx.x;
    float v[8];
    float mx = -3.4e38f;
    #pragma unroll
    for (int i = 0; i < 8; i++) { v[i] = p[t + i*256]; mx = fmaxf(mx, v[i]); }
    __shared__ float red[8], red2[8];
    #pragma unroll
    for (int o = 16; o; o >>= 1) mx = fmaxf(mx, __shfl_xor_sync(0xffffffffu, mx, o));
    if ((t & 31) == 0) red[t >> 5] = mx;
    __syncthreads();
    mx = red[0];
    #pragma unroll
    for (int i = 1; i < 8; i++) mx = fmaxf(mx, red[i]);
    float s = 0.f;
    #pragma unroll
    for (int i = 0; i < 8; i++) { v[i] = __expf(v[i] - mx); s += v[i]; }
    #pragma unroll
    for (int o = 16; o; o >>= 1) s += __shfl_xor_sync(0xffffffffu, s, o);
    if ((t & 31) == 0) red2[t >> 5] = s;
    __syncthreads();
    s = 0.f;
    #pragma unroll
    for (int i = 0; i < 8; i++) s += red2[i];
    const float inv = 1.0f / s;
    const size_t rb = (size_t)blockIdx.x * H_;
    #pragma unroll
    for (int i = 0; i < 8; i++) {
        float f = v[i] * inv;
        __nv_bfloat16 hh, ll;
        split2(f, hh, ll);
        ph[rb + t + i*256] = hh;
        pl[rb + t + i*256] = ll;
    }
}

// ---------------- launch ---------------------------------------------------
extern "C" void kernel_launch(void* const* d_in, const int* in_sizes, int n_in,
                              void* d_out, int out_size)
{
    (void)in_sizes; (void)n_in; (void)out_size;
    const float* x     = (const float*)d_in[0];
    const float* gamma = (const float*)d_in[1];
    const float* beta  = (const float*)d_in[2];
    const float* wq    = (const float*)d_in[3];
    const float* bq    = (const float*)d_in[4];
    const float* wk    = (const float*)d_in[5];
    const float* bk    = (const float*)d_in[6];
    const float* wv    = (const float*)d_in[7];
    const float* bv    = (const float*)d_in[8];
    const float* wp    = (const float*)d_in[9];
    const float* bp    = (const float*)d_in[10];
    float* out = (float*)d_out;

    __nv_bfloat16 *hnTh, *hnTl, *qTh, *qTl, *kTh, *kTl, *vh, *vl, *hTh, *hTl;
    __nv_bfloat16 *ph, *pl, *wqh, *wql, *wkh, *wkl, *wvh, *wvl, *wph, *wpl;
    float* w;
    cudaGetSymbolAddress((void**)&hnTh, g_hnT_h); cudaGetSymbolAddress((void**)&hnTl, g_hnT_l);
    cudaGetSymbolAddress((void**)&qTh, g_qT_h);   cudaGetSymbolAddress((void**)&qTl, g_qT_l);
    cudaGetSymbolAddress((void**)&kTh, g_kT_h);   cudaGetSymbolAddress((void**)&kTl, g_kT_l);
    cudaGetSymbolAddress((void**)&vh,  g_v_h);    cudaGetSymbolAddress((void**)&vl,  g_v_l);
    cudaGetSymbolAddress((void**)&hTh, g_hT_h);   cudaGetSymbolAddress((void**)&hTl, g_hT_l);
    cudaGetSymbolAddress((void**)&w,   g_w);
    cudaGetSymbolAddress((void**)&ph,  g_p_h);    cudaGetSymbolAddress((void**)&pl,  g_p_l);
    cudaGetSymbolAddress((void**)&wqh, g_wq_h);   cudaGetSymbolAddress((void**)&wql, g_wq_l);
    cudaGetSymbolAddress((void**)&wkh, g_wk_h);   cudaGetSymbolAddress((void**)&wkl, g_wk_l);
    cudaGetSymbolAddress((void**)&wvh, g_wv_h);   cudaGetSymbolAddress((void**)&wvl, g_wv_l);
    cudaGetSymbolAddress((void**)&wph, g_wp_h);   cudaGetSymbolAddress((void**)&wpl, g_wp_l);

    cudaFuncSetAttribute(mma_gemm<0>, cudaFuncAttributeMaxDynamicSharedMemorySize, SMEM_SZ);
    cudaFuncSetAttribute(mma_gemm<1>, cudaFuncAttributeMaxDynamicSharedMemorySize, SMEM_SZ);
    cudaFuncSetAttribute(mma_gemm<2>, cudaFuncAttributeMaxDynamicSharedMemorySize, SMEM_SZ);
    cudaFuncSetAttribute(mma_gemm<3>, cudaFuncAttributeMaxDynamicSharedMemorySize, SMEM_SZ);
    cudaFuncSetAttribute(mma_gemm<4>, cudaFuncAttributeMaxDynamicSharedMemorySize, SMEM_SZ);

    const float scale = 0.044194173824159216f;  // 512^-0.5

    groupnorm_kernel<<<B_ * 32, 256>>>(x, gamma, beta, hnTh, hnTl);
    split_kernel<<<1024, 256>>>(wq, wqh, wql, C_*C_);
    split_kernel<<<1024, 256>>>(wk, wkh, wkl, C_*C_);
    split_kernel<<<1024, 256>>>(wv, wvh, wvl, C_*C_);
    split_kernel<<<1024, 256>>>(wp, wph, wpl, C_*C_);

    dim3 gc(H_ / 128, C_ / 128, B_);   // (16, 4, 8)
    dim3 gs(H_ / 128, H_ / 128, B_);   // (16, 16, 8)

    // Q = Wq @ hn -> qT[h][c] split (M=C, N=H, K=C)
    mma_gemm<0><<<gc, 256, SMEM_SZ>>>(wqh, wql, hnTh, hnTl, C_, 0, CH_,
        nullptr, 0, qTh, qTl, CH_, bq, nullptr, 1.f);
    mma_gemm<0><<<gc, 256, SMEM_SZ>>>(wkh, wkl, hnTh, hnTl, C_, 0, CH_,
        nullptr, 0, kTh, kTl, CH_, bk, nullptr, 1.f);
    // V row-major [c][h] split
    mma_gemm<1><<<gc, 256, SMEM_SZ>>>(wvh, wvl, hnTh, hnTl, C_, 0, CH_,
        nullptr, 0, vh, vl, CH_, bv, nullptr, 1.f);
    // scores[i][j] = scale * qT[i]·kT[j]
    mma_gemm<2><<<gs, 256, SMEM_SZ>>>(qTh, qTl, kTh, kTl, C_, CH_, CH_,
        w, HH_, nullptr, nullptr, 0, nullptr, nullptr, scale);
    softmax_kernel<<<B_ * H_, 256>>>(w, ph, pl);
    // h[c][i] = v[c]·p[i] -> hT[i][c] split
    mma_gemm<3><<<gc, 256, SMEM_SZ>>>(vh, vl, ph, pl, H_, CH_, HH_,
        nullptr, 0, hTh, hTl, CH_, nullptr, nullptr, 1.f);
    // out = Wp @ h + bp + x
    mma_gemm<4><<<gc, 256, SMEM_SZ>>>(wph, wpl, hTh, hTl, C_, 0, CH_,
        out, CH_, nullptr, nullptr, 0, bp, x, 1.f);
}

// round 6
// speedup vs baseline: 5.1562x; 2.4049x over previous
#include <cuda_runtime.h>
#include <cuda_fp16.h>
#include <cstdint>
#include <cstddef>

#define B_ 8
#define C_ 512
#define H_ 2048
#define CG_ 16
#define CH_ 1048576LL      // C*H
#define HH_ 4194304LL      // H*H
#define BCH_ 8388608LL     // B*C*H
#define BHH_ 33554432LL    // B*H*H

// ---------------- scratch (device globals) ---------------------------------
__device__ __half g_hnT[BCH_];     // [B][H][C]
__device__ __half g_qT[BCH_];      // [B][H][C]
__device__ __half g_kT[BCH_];      // [B][H][C]
__device__ __half g_v[BCH_];       // [B][C][H]
__device__ __half g_hT[BCH_];      // [B][H][C]
__device__ __half g_s[BHH_];       // scores [B][H][H] fp16
__device__ __half g_p[BHH_];       // probs  [B][H][H] fp16
__device__ __half g_wq[C_*C_], g_wk[C_*C_], g_wv[C_*C_], g_wp[C_*C_];

// ---------------- helpers --------------------------------------------------
__device__ __forceinline__ uint32_t smem_to_u32(const void* p) {
    uint32_t a;
    asm("{ .reg .u64 t; cvta.to.shared.u64 t, %1; cvt.u32.u64 %0, t; }"
        : "=r"(a) : "l"(p));
    return a;
}
#define CP16(dst, src) \
    asm volatile("cp.async.cg.shared.global [%0], [%1], 16;" :: "r"(dst), "l"(src))
#define CP_COMMIT()  asm volatile("cp.async.commit_group;" ::: "memory")
#define CP_WAIT2()   asm volatile("cp.async.wait_group 2;" ::: "memory")
#define LDM4(R, addr) \
    asm volatile("ldmatrix.sync.aligned.m8n8.x4.shared.b16 {%0,%1,%2,%3}, [%4];" \
        : "=r"((R)[0]), "=r"((R)[1]), "=r"((R)[2]), "=r"((R)[3]) : "r"(addr))
#define HMMA(d, a, b0, b1) \
    asm volatile("mma.sync.aligned.m16n8k16.row.col.f32.f16.f16.f32 " \
        "{%0,%1,%2,%3}, {%4,%5,%6,%7}, {%8,%9}, {%0,%1,%2,%3};" \
        : "+f"((d)[0]), "+f"((d)[1]), "+f"((d)[2]), "+f"((d)[3]) \
        : "r"((a)[0]), "r"((a)[1]), "r"((a)[2]), "r"((a)[3]), "r"(b0), "r"(b1))

// ---------------- GroupNorm: x[b,c,h] -> hnT[b,h,c] fp16 -------------------
__global__ __launch_bounds__(256) void groupnorm_kernel(
    const float* __restrict__ x, const float* __restrict__ gamma,
    const float* __restrict__ beta, __half* __restrict__ oh)
{
    const int b = blockIdx.x >> 5;
    const int g = blockIdx.x & 31;
    const size_t base = ((size_t)b * C_ + (size_t)g * CG_) * H_;
    const float4* xp4 = (const float4*)(x + base);
    const int t = threadIdx.x;

    __shared__ float rs[8], rs2[8];
    __shared__ float gmv[16], btv[16];
    __shared__ float tile[16][257];

    float s = 0.f, s2 = 0.f;
    for (int i = t; i < (CG_ * H_) / 4; i += 256) {
        float4 v = xp4[i];
        s  += v.x + v.y + v.z + v.w;
        s2 += v.x*v.x + v.y*v.y + v.z*v.z + v.w*v.w;
    }
    #pragma unroll
    for (int o = 16; o; o >>= 1) {
        s  += __shfl_xor_sync(0xffffffffu, s,  o);
        s2 += __shfl_xor_sync(0xffffffffu, s2, o);
    }
    if ((t & 31) == 0) { rs[t >> 5] = s; rs2[t >> 5] = s2; }
    __syncthreads();
    if (t == 0) {
        float S = 0.f, S2 = 0.f;
        #pragma unroll
        for (int i = 0; i < 8; i++) { S += rs[i]; S2 += rs2[i]; }
        const float inv_n = 1.0f / (CG_ * H_);
        float mean = S * inv_n;
        float var  = S2 * inv_n - mean * mean;
        rs[0]  = mean;
        rs2[0] = rsqrtf(var + 1e-6f);
    }
    __syncthreads();
    if (t < 16) {
        int c = g * CG_ + t;
        float gm = gamma[c] * rs2[0];
        gmv[t] = gm;
        btv[t] = beta[c] - rs[0] * gm;
    }
    __syncthreads();

    for (int hc = 0; hc < H_; hc += 256) {
        #pragma unroll
        for (int r = 0; r < 16; r++)
            tile[r][t] = x[base + (size_t)r * H_ + hc + t];
        __syncthreads();
        alignas(16) __half hh[16];
        #pragma unroll
        for (int c = 0; c < 16; c++)
            hh[c] = __float2half(tile[c][t] * gmv[c] + btv[c]);
        size_t o = (size_t)b * H_ * C_ + (size_t)(hc + t) * C_ + g * CG_;
        *(uint4*)(oh + o)     = *(uint4*)hh;
        *(uint4*)(oh + o + 8) = *(uint4*)(hh + 8);
        __syncthreads();
    }
}

// ---------------- weight convert (all 4 at once) ---------------------------
__global__ __launch_bounds__(256) void wconv_kernel(
    const float* __restrict__ w0, const float* __restrict__ w1,
    const float* __restrict__ w2, const float* __restrict__ w3,
    __half* __restrict__ o0, __half* __restrict__ o1,
    __half* __restrict__ o2, __half* __restrict__ o3)
{
    int i = blockIdx.x * 256 + threadIdx.x;      // grid covers 4*C*C
    int sel = i >> 18;                            // C*C = 262144 = 2^18
    int j = i & 0x3FFFF;
    const float* s = (sel == 0) ? w0 : (sel == 1) ? w1 : (sel == 2) ? w2 : w3;
    __half* d      = (sel == 0) ? o0 : (sel == 1) ? o1 : (sel == 2) ? o2 : o3;
    d[j] = __float2half(s[j]);
}

// ---------------- fp16 mma GEMM --------------------------------------------
// D[m,n] = sum_k A[m,k]*B[n,k]; A,B fp16, K-contiguous rows.
// CTA 128x128, BK=32, 4-stage cp.async, 8 warps (4m x 2n), warp 32x64.
// EPI: 0 transposed half +bias; 1 row half +bias; 2 row half *alpha;
//      3 transposed half no-bias; 4 fp32 +bias +resid.
#define STAGE_B 20480
#define OFF_A   0
#define OFF_B   10240
#define SMEM_SZ (4 * STAGE_B)    // 81920

template<int EPI>
__global__ __launch_bounds__(256) void mma_gemm(
    const __half* __restrict__ A, const __half* __restrict__ B,
    int K, long long sA, long long sB,
    float* __restrict__ Cf, long long sC,
    __half* __restrict__ Oh, long long sO,
    const float* __restrict__ bias, const float* __restrict__ resid, float alpha)
{
    extern __shared__ __align__(128) char smem[];
    const uint32_t su = smem_to_u32(smem);
    const int t    = threadIdx.x;
    const int lane = t & 31;
    const int w    = t >> 5;
    const int wm   = w >> 1;
    const int wn   = w & 1;
    const int bz = blockIdx.z;
    const int bm = blockIdx.y * 128;
    const int bn = blockIdx.x * 128;
    const int Ntot = gridDim.x * 128;
    const int Mtot = gridDim.y * 128;

    const int lrow  = t >> 1;
    const int lhalf = t & 1;
    const uint32_t dofs = (uint32_t)(lrow * 80 + lhalf * 32);
    const __half* pA = A + (size_t)bz * sA + (size_t)(bm + lrow) * K + lhalf * 16;
    const __half* pB = B + (size_t)bz * sB + (size_t)(bn + lrow) * K + lhalf * 16;

    float acc[2][8][4];
    #pragma unroll
    for (int a = 0; a < 2; a++)
        #pragma unroll
        for (int b = 0; b < 8; b++)
            #pragma unroll
            for (int c = 0; c < 4; c++) acc[a][b][c] = 0.f;

    const int niter = K >> 5;

#define LOAD_STAGE(s, ci) do { \
    uint32_t d = su + (uint32_t)(s) * STAGE_B + dofs; \
    const __half* a_ = pA + (size_t)(ci) * 32; \
    const __half* b_ = pB + (size_t)(ci) * 32; \
    CP16(d + OFF_A, a_); CP16(d + OFF_A + 16, a_ + 8); \
    CP16(d + OFF_B, b_); CP16(d + OFF_B + 16, b_ + 8); \
} while (0)

    LOAD_STAGE(0, 0); CP_COMMIT();
    LOAD_STAGE(1, 1); CP_COMMIT();
    LOAD_STAGE(2, 2); CP_COMMIT();

    const int arow = lane & 15;
    const int akof = (lane >> 4) * 8;
    const int brow = (lane & 7) + (lane >> 4) * 8;
    const int bkof = ((lane >> 3) & 1) * 8;

    for (int i = 0; i < niter; i++) {
        CP_WAIT2();
        __syncthreads();
        const int ls = i + 3;
        if (ls < niter) LOAD_STAGE((ls & 3), ls);
        CP_COMMIT();

        const uint32_t base = su + (uint32_t)(i & 3) * STAGE_B;
        const uint32_t As = base + OFF_A, Bs = base + OFF_B;
        #pragma unroll
        for (int ks = 0; ks < 2; ks++) {
            const int k0 = ks * 16;
            uint32_t a[2][4], b[4][4];
            #pragma unroll
            for (int mt = 0; mt < 2; mt++) {
                uint32_t ro = (uint32_t)((wm * 32 + mt * 16 + arow) * 80 + (k0 + akof) * 2);
                LDM4(a[mt], As + ro);
            }
            #pragma unroll
            for (int p = 0; p < 4; p++) {
                uint32_t ro = (uint32_t)((wn * 64 + p * 16 + brow) * 80 + (k0 + bkof) * 2);
                LDM4(b[p], Bs + ro);
            }
            #pragma unroll
            for (int mt = 0; mt < 2; mt++)
                #pragma unroll
                for (int p = 0; p < 4; p++) {
                    HMMA(acc[mt][2*p],   a[mt], b[p][0], b[p][1]);
                    HMMA(acc[mt][2*p+1], a[mt], b[p][2], b[p][3]);
                }
        }
    }
#undef LOAD_STAGE

    __syncthreads();

    const int g4 = lane >> 2, t4 = lane & 3;

    if (EPI == 2) {
        #pragma unroll
        for (int mt = 0; mt < 2; mt++) {
            const int R0 = bm + wm * 32 + mt * 16 + g4;
            #pragma unroll
            for (int nt = 0; nt < 8; nt++) {
                const int Cc = bn + wn * 64 + nt * 8 + t4 * 2;
                __half2 v0 = __floats2half2_rn(acc[mt][nt][0] * alpha, acc[mt][nt][1] * alpha);
                __half2 v1 = __floats2half2_rn(acc[mt][nt][2] * alpha, acc[mt][nt][3] * alpha);
                *(__half2*)(Oh + (size_t)bz * sO + (size_t)R0 * Ntot + Cc) = v0;
                *(__half2*)(Oh + (size_t)bz * sO + (size_t)(R0 + 8) * Ntot + Cc) = v1;
            }
        }
    } else if (EPI == 4) {
        #pragma unroll
        for (int mt = 0; mt < 2; mt++) {
            const int R0 = bm + wm * 32 + mt * 16 + g4;
            const float bi0 = bias[R0], bi1 = bias[R0 + 8];
            #pragma unroll
            for (int nt = 0; nt < 8; nt++) {
                const int Cc = bn + wn * 64 + nt * 8 + t4 * 2;
                const size_t i0 = (size_t)bz * sC + (size_t)R0 * Ntot + Cc;
                const size_t i1 = (size_t)bz * sC + (size_t)(R0 + 8) * Ntot + Cc;
                float2 q0 = *(const float2*)(resid + i0);
                float2 q1 = *(const float2*)(resid + i1);
                float2 v0 = { acc[mt][nt][0] + bi0 + q0.x, acc[mt][nt][1] + bi0 + q0.y };
                float2 v1 = { acc[mt][nt][2] + bi1 + q1.x, acc[mt][nt][3] + bi1 + q1.y };
                *(float2*)(Cf + i0) = v0;
                *(float2*)(Cf + i1) = v1;
            }
        }
    } else if (EPI == 1) {
        #pragma unroll
        for (int mt = 0; mt < 2; mt++) {
            const int R0 = bm + wm * 32 + mt * 16 + g4;
            const float bi0 = bias[R0], bi1 = bias[R0 + 8];
            #pragma unroll
            for (int nt = 0; nt < 8; nt++) {
                const int Cc = bn + wn * 64 + nt * 8 + t4 * 2;
                __half2 v0 = __floats2half2_rn(acc[mt][nt][0] + bi0, acc[mt][nt][1] + bi0);
                __half2 v1 = __floats2half2_rn(acc[mt][nt][2] + bi1, acc[mt][nt][3] + bi1);
                *(__half2*)(Oh + (size_t)bz * sO + (size_t)R0 * Ntot + Cc) = v0;
                *(__half2*)(Oh + (size_t)bz * sO + (size_t)(R0 + 8) * Ntot + Cc) = v1;
            }
        }
    } else {   // EPI 0 / 3: transposed store via smem staging
        __half* sh = (__half*)smem;   // [128 n][136 m pad]
        #pragma unroll
        for (int mt = 0; mt < 2; mt++) {
            const int Rl = wm * 32 + mt * 16 + g4;
            const float bi0 = (EPI == 0) ? bias[bm + Rl] : 0.f;
            const float bi1 = (EPI == 0) ? bias[bm + Rl + 8] : 0.f;
            #pragma unroll
            for (int nt = 0; nt < 8; nt++) {
                const int Cl = wn * 64 + nt * 8 + t4 * 2;
                sh[Cl * 136 + Rl]           = __float2half(acc[mt][nt][0] + bi0);
                sh[(Cl + 1) * 136 + Rl]     = __float2half(acc[mt][nt][1] + bi0);
                sh[Cl * 136 + Rl + 8]       = __float2half(acc[mt][nt][2] + bi1);
                sh[(Cl + 1) * 136 + Rl + 8] = __float2half(acc[mt][nt][3] + bi1);
            }
        }
        __syncthreads();
        const int nrow = t >> 5;
        const int m4   = lane * 4;
        #pragma unroll
        for (int it = 0; it < 16; it++) {
            const int n = it * 8 + nrow;
            uint2 vh = *(uint2*)(sh + n * 136 + m4);
            *(uint2*)(Oh + (size_t)bz * sO + (size_t)(bn + n) * Mtot + bm + m4) = vh;
        }
    }
}

// ---------------- Softmax: fp16 scores row -> fp16 probs -------------------
__global__ __launch_bounds__(256) void softmax_kernel(
    const __half* __restrict__ w, __half* __restrict__ ph)
{
    const __half2* p = (const __half2*)(w + (size_t)blockIdx.x * H_);
    __half2* po = (__half2*)(ph + (size_t)blockIdx.x * H_);
    const int t = threadIdx.x;
    float2 v[4];
    float mx = -3.4e38f;
    #pragma unroll
    for (int i = 0; i < 4; i++) {
        v[i] = __half22float2(p[t + i * 256]);
        mx = fmaxf(mx, fmaxf(v[i].x, v[i].y));
    }
    __shared__ float red[8], red2[8];
    #pragma unroll
    for (int o = 16; o; o >>= 1) mx = fmaxf(mx, __shfl_xor_sync(0xffffffffu, mx, o));
    if ((t & 31) == 0) red[t >> 5] = mx;
    __syncthreads();
    mx = red[0];
    #pragma unroll
    for (int i = 1; i < 8; i++) mx = fmaxf(mx, red[i]);
    float s = 0.f;
    #pragma unroll
    for (int i = 0; i < 4; i++) {
        v[i].x = __expf(v[i].x - mx);
        v[i].y = __expf(v[i].y - mx);
        s += v[i].x + v[i].y;
    }
    #pragma unroll
    for (int o = 16; o; o >>= 1) s += __shfl_xor_sync(0xffffffffu, s, o);
    if ((t & 31) == 0) red2[t >> 5] = s;
    __syncthreads();
    s = 0.f;
    #pragma unroll
    for (int i = 0; i < 8; i++) s += red2[i];
    const float inv = 1.0f / s;
    #pragma unroll
    for (int i = 0; i < 4; i++)
        po[t + i * 256] = __floats2half2_rn(v[i].x * inv, v[i].y * inv);
}

// ---------------- launch ---------------------------------------------------
extern "C" void kernel_launch(void* const* d_in, const int* in_sizes, int n_in,
                              void* d_out, int out_size)
{
    (void)in_sizes; (void)n_in; (void)out_size;
    const float* x     = (const float*)d_in[0];
    const float* gamma = (const float*)d_in[1];
    const float* beta  = (const float*)d_in[2];
    const float* wq    = (const float*)d_in[3];
    const float* bq    = (const float*)d_in[4];
    const float* wk    = (const float*)d_in[5];
    const float* bk    = (const float*)d_in[6];
    const float* wv    = (const float*)d_in[7];
    const float* bv    = (const float*)d_in[8];
    const float* wp    = (const float*)d_in[9];
    const float* bp    = (const float*)d_in[10];
    float* out = (float*)d_out;

    __half *hnT, *qT, *kT, *v, *hT, *sc, *pr, *hwq, *hwk, *hwv, *hwp;
    cudaGetSymbolAddress((void**)&hnT, g_hnT);
    cudaGetSymbolAddress((void**)&qT,  g_qT);
    cudaGetSymbolAddress((void**)&kT,  g_kT);
    cudaGetSymbolAddress((void**)&v,   g_v);
    cudaGetSymbolAddress((void**)&hT,  g_hT);
    cudaGetSymbolAddress((void**)&sc,  g_s);
    cudaGetSymbolAddress((void**)&pr,  g_p);
    cudaGetSymbolAddress((void**)&hwq, g_wq);
    cudaGetSymbolAddress((void**)&hwk, g_wk);
    cudaGetSymbolAddress((void**)&hwv, g_wv);
    cudaGetSymbolAddress((void**)&hwp, g_wp);

    cudaFuncSetAttribute(mma_gemm<0>, cudaFuncAttributeMaxDynamicSharedMemorySize, SMEM_SZ);
    cudaFuncSetAttribute(mma_gemm<1>, cudaFuncAttributeMaxDynamicSharedMemorySize, SMEM_SZ);
    cudaFuncSetAttribute(mma_gemm<2>, cudaFuncAttributeMaxDynamicSharedMemorySize, SMEM_SZ);
    cudaFuncSetAttribute(mma_gemm<3>, cudaFuncAttributeMaxDynamicSharedMemorySize, SMEM_SZ);
    cudaFuncSetAttribute(mma_gemm<4>, cudaFuncAttributeMaxDynamicSharedMemorySize, SMEM_SZ);

    const float scale = 0.044194173824159216f;  // 512^-0.5

    groupnorm_kernel<<<B_ * 32, 256>>>(x, gamma, beta, hnT);
    wconv_kernel<<<4096, 256>>>(wq, wk, wv, wp, hwq, hwk, hwv, hwp);

    dim3 gc(H_ / 128, C_ / 128, B_);   // (16, 4, 8)
    dim3 gs(H_ / 128, H_ / 128, B_);   // (16, 16, 8)

    // Q = Wq @ hn -> qT[h][c]   (M=C, N=H, K=C)
    mma_gemm<0><<<gc, 256, SMEM_SZ>>>(hwq, hnT, C_, 0, CH_,
        nullptr, 0, qT, CH_, bq, nullptr, 1.f);
    mma_gemm<0><<<gc, 256, SMEM_SZ>>>(hwk, hnT, C_, 0, CH_,
        nullptr, 0, kT, CH_, bk, nullptr, 1.f);
    // V row-major [c][h]
    mma_gemm<1><<<gc, 256, SMEM_SZ>>>(hwv, hnT, C_, 0, CH_,
        nullptr, 0, v, CH_, bv, nullptr, 1.f);
    // scores[i][j] = scale * qT[i]·kT[j]  -> fp16
    mma_gemm<2><<<gs, 256, SMEM_SZ>>>(qT, kT, C_, CH_, CH_,
        nullptr, 0, sc, HH_, nullptr, nullptr, scale);
    softmax_kernel<<<B_ * H_, 256>>>(sc, pr);
    // h[c][i] = v[c]·p[i] -> hT[i][c]
    mma_gemm<3><<<gc, 256, SMEM_SZ>>>(v, pr, H_, CH_, HH_,
        nullptr, 0, hT, CH_, nullptr, nullptr, 1.f);
    // out = Wp @ h + bp + x
    mma_gemm<4><<<gc, 256, SMEM_SZ>>>(hwp, hT, C_, 0, CH_,
        out, CH_, nullptr, 0, bp, x, 1.f);
}